// round 16
// baseline (speedup 1.0000x reference)
#include <cuda_runtime.h>
#include <math.h>

#define BB    2
#define NQQ   900
#define EE    256
#define NH    8
#define HDIM  32
#define HWK   4096
#define RPEH  512
#define LOG2E_F 1.4426950408889634f
#define QSCALE_F 0.17677669529663687f
#define NSPLIT 4
#define QPAD   960

__device__ float g_qT[BB * NH * HDIM * NQQ + 1024];
__device__ float g_kT[BB * NH * HDIM * HWK];
__device__ float g_v [BB * HWK * EE];
__device__ float g_rx[BB * NH * NQQ * 64];
__device__ float g_ryT[BB * NH * 64 * NQQ];
__device__ float g_att[BB * NQQ * EE];
__device__ float g_po[NSPLIT * BB * NH * QPAD * HDIM];
__device__ float g_pl[NSPLIT * BB * NH * QPAD];

typedef unsigned long long u64;

__device__ __forceinline__ float fexp2(float x) {
    float y; asm("ex2.approx.ftz.f32 %0, %1;" : "=f"(y) : "f"(x)); return y;
}
__device__ __forceinline__ u64 ffma2(u64 a, u64 b, u64 c) {
    u64 d; asm("fma.rn.f32x2 %0, %1, %2, %3;" : "=l"(d) : "l"(a), "l"(b), "l"(c)); return d;
}
__device__ __forceinline__ u64 fmul2(u64 a, u64 b) {
    u64 d; asm("mul.rn.f32x2 %0, %1, %2;" : "=l"(d) : "l"(a), "l"(b)); return d;
}
__device__ __forceinline__ u64 dup2(float x) {
    u64 r; asm("mov.b64 %0, {%1, %1};" : "=l"(r) : "f"(x)); return r;
}
__device__ __forceinline__ float2 unpk2(u64 v) {
    float2 r; asm("mov.b64 {%0, %1}, %2;" : "=f"(r.x), "=f"(r.y) : "l"(v)); return r;
}
__device__ __forceinline__ float logdelta(float d) {
    float l = log2f(fabsf(d) + 1.0f) * (1.0f / 3.0f);
    return copysignf(l, d);
}

// ---------------------------------------------------------------------------
template<int TMODE>
__global__ void gemm_bias_kernel(const float* __restrict__ A,
                                 const float* __restrict__ Wm,
                                 const float* __restrict__ bias,
                                 float* __restrict__ C,
                                 int M, int plane, float alpha)
{
    __shared__ __align__(16) float As[16][64];
    __shared__ __align__(16) float Ws[16][64];

    int tid = threadIdx.x;
    int m0 = blockIdx.x * 64;
    int n0 = blockIdx.y * 64;
    int tm = tid >> 4, tn = tid & 15;
    int lrow = tid >> 2, lkq = tid & 3;
    int wkk = tid >> 4, wnq = tid & 15;

    u64 acc2[4][2] = {};

    for (int k0 = 0; k0 < 256; k0 += 16) {
        float4 av = make_float4(0.f, 0.f, 0.f, 0.f);
        int m = m0 + lrow;
        if (m < M) av = *(const float4*)&A[m * 256 + k0 + 4 * lkq];
        As[4 * lkq + 0][lrow] = av.x;
        As[4 * lkq + 1][lrow] = av.y;
        As[4 * lkq + 2][lrow] = av.z;
        As[4 * lkq + 3][lrow] = av.w;
        *(float4*)&Ws[wkk][4 * wnq] =
            *(const float4*)&Wm[(k0 + wkk) * 256 + n0 + 4 * wnq];
        __syncthreads();

        #pragma unroll
        for (int kk = 0; kk < 16; kk++) {
            float4 a = *(const float4*)&As[kk][4 * tm];
            ulonglong2 w = *(const ulonglong2*)&Ws[kk][4 * tn];
            float ar[4] = {a.x, a.y, a.z, a.w};
            #pragma unroll
            for (int i = 0; i < 4; i++) {
                u64 ad = dup2(ar[i]);
                acc2[i][0] = ffma2(ad, w.x, acc2[i][0]);
                acc2[i][1] = ffma2(ad, w.y, acc2[i][1]);
            }
        }
        __syncthreads();
    }

    float4 bv = *(const float4*)&bias[n0 + 4 * tn];
    float o[4][4];
    #pragma unroll
    for (int i = 0; i < 4; i++) {
        float2 lo = unpk2(acc2[i][0]);
        float2 hi = unpk2(acc2[i][1]);
        o[i][0] = alpha * (lo.x + bv.x);
        o[i][1] = alpha * (lo.y + bv.y);
        o[i][2] = alpha * (hi.x + bv.z);
        o[i][3] = alpha * (hi.y + bv.w);
    }

    if (TMODE == 0) {
        #pragma unroll
        for (int i = 0; i < 4; i++) {
            int m = m0 + 4 * tm + i;
            if (m < M)
                *(float4*)&C[m * 256 + n0 + 4 * tn] =
                    make_float4(o[i][0], o[i][1], o[i][2], o[i][3]);
        }
    } else {
        __shared__ float Ts[64][65];
        #pragma unroll
        for (int i = 0; i < 4; i++)
            #pragma unroll
            for (int j = 0; j < 4; j++)
                Ts[4 * tn + j][4 * tm + i] = o[i][j];
        __syncthreads();
        for (int idx = tid; idx < 4096; idx += 256) {
            int ml = idx & 63, nl = idx >> 6;
            int m = m0 + ml;
            if (m < M) {
                int bq = m / plane;
                int mm = m - bq * plane;
                int n = n0 + nl;
                int row = (bq * NH + (n >> 5)) * 32 + (n & 31);
                C[(long long)row * plane + mm] = Ts[nl][ml];
            }
        }
    }
}

// ---------------------------------------------------------------------------
// RPE MLP (verified): grid (450, 2), 128 threads.
// ---------------------------------------------------------------------------
__global__ void rpe_kernel(const float* __restrict__ refp,
                           const float* __restrict__ W1x, const float* __restrict__ b1x,
                           const float* __restrict__ W2x,
                           const float* __restrict__ W1y, const float* __restrict__ b1y,
                           const float* __restrict__ W2y)
{
    __shared__ __align__(16) float4 sW1p[RPEH];
    __shared__ __align__(16) float sW2[RPEH * 8];

    int tid = threadIdx.x;
    int axis = blockIdx.y;
    const float* W1 = axis ? W1y : W1x;
    const float* b1 = axis ? b1y : b1x;
    const float* W2 = axis ? W2y : W2x;

    for (int i = tid; i < RPEH; i += 128)
        sW1p[i] = make_float4(W1[i], W1[RPEH + i], b1[i], 0.0f);
    for (int i = tid; i < RPEH * 8; i += 128)
        sW2[i] = W2[i];
    __syncthreads();

    int bq = blockIdx.x * 4 + (tid >> 5);
    int b = bq / NQQ, q = bq - b * NQQ;
    float4 r = *(const float4*)&refp[bq * 4];
    int lane = tid & 31;

    float ctr = axis ? r.y : r.x;
    float sz  = axis ? r.w : r.z;
    float lo = (ctr - 0.5f * sz) * 1024.0f;
    float hi = (ctr + 0.5f * sz) * 1024.0f;
    float posA = (lane + 0.5f) * 16.0f;
    float posB = (lane + 32.5f) * 16.0f;
    float d1a = logdelta(lo - posA), d2a = logdelta(hi - posA);
    float d1b = logdelta(lo - posB), d2b = logdelta(hi - posB);

    u64 a0[4] = {}, a1[4] = {};
    #pragma unroll 4
    for (int hh = 0; hh < RPEH; hh++) {
        float4 w = sW1p[hh];
        float v0 = fmaxf(fmaf(d1a, w.x, fmaf(d2a, w.y, w.z)), 0.0f);
        float v1 = fmaxf(fmaf(d1b, w.x, fmaf(d2b, w.y, w.z)), 0.0f);
        u64 v0d = dup2(v0), v1d = dup2(v1);
        ulonglong2 wlo = *(const ulonglong2*)&sW2[hh * 8];
        ulonglong2 whi = *(const ulonglong2*)&sW2[hh * 8 + 4];
        a0[0] = ffma2(v0d, wlo.x, a0[0]);  a0[1] = ffma2(v0d, wlo.y, a0[1]);
        a0[2] = ffma2(v0d, whi.x, a0[2]);  a0[3] = ffma2(v0d, whi.y, a0[3]);
        a1[0] = ffma2(v1d, wlo.x, a1[0]);  a1[1] = ffma2(v1d, wlo.y, a1[1]);
        a1[2] = ffma2(v1d, whi.x, a1[2]);  a1[3] = ffma2(v1d, whi.y, a1[3]);
    }

    float o0[8], o1[8];
    #pragma unroll
    for (int c = 0; c < 4; c++) {
        float2 x0 = unpk2(a0[c]); float2 x1 = unpk2(a1[c]);
        o0[2*c] = x0.x * LOG2E_F;  o0[2*c+1] = x0.y * LOG2E_F;
        o1[2*c] = x1.x * LOG2E_F;  o1[2*c+1] = x1.y * LOG2E_F;
    }
    long long bh = (long long)b * NH;
    #pragma unroll
    for (int hd = 0; hd < 8; hd++) {
        if (axis == 0) {
            g_rx[((bh + hd) * NQQ + q) * 64 + lane]      = o0[hd];
            g_rx[((bh + hd) * NQQ + q) * 64 + lane + 32] = o1[hd];
        } else {
            g_ryT[((bh + hd) * 64 + lane)      * NQQ + q] = o0[hd];
            g_ryT[((bh + hd) * 64 + lane + 32) * NQQ + q] = o1[hd];
        }
    }
}

// ---------------------------------------------------------------------------
// Fused attention v7: v6 + rx held in REGISTERS (rxsT smem tile deleted),
// V prefetch moved after barrier 1 (shorter register lifetime).
// smem 42.2 KB => 4-5 blocks/SM (16-20 warps). No softmax reductions in loop.
// ---------------------------------------------------------------------------
#define OFF_K    2048     // 2 x [32 d][32 k]
#define OFF_V    4096     // [64 k][32 d]
#define OFF_ST   6144     // [64 k][68]
#define OFF_RY   10496    // [64]
#define ATTN_SMEM_FLOATS 10560

__global__ void __launch_bounds__(128, 4) attn_kernel()
{
    extern __shared__ __align__(16) float sm[];
    float* QsT = sm;
    float* Ks  = sm + OFF_K;
    float* Vs  = sm + OFF_V;
    float* ST  = sm + OFF_ST;
    float* ryc = sm + OFF_RY;

    int tid = threadIdx.x;
    int qt = blockIdx.x, h = blockIdx.y;
    int b = blockIdx.z >> 2, sp = blockIdx.z & 3;
    int q0 = qt * 64;
    int tq = tid >> 3, tx = tid & 7;
    int swz = 4 * ((tq ^ tx) & 15);
    long long bh = (long long)b * NH + h;

    // Q tile
    {
        int q4 = (tid & 15) * 4;
        int dr = tid >> 4;
        const float* qb = g_qT + bh * 32 * NQQ;
        #pragma unroll
        for (int r2 = 0; r2 < 4; r2++) {
            int d = dr + 8 * r2;
            float4 val = make_float4(0.f, 0.f, 0.f, 0.f);
            if (q0 + q4 < NQQ) val = *(const float4*)&qb[d * NQQ + q0 + q4];
            *(float4*)&QsT[d * 64 + q4] = val;
        }
    }

    // rx values for this thread's 4 q x 8 w tile -> registers
    float rxr[4][8];
    {
        const float* rxb = g_rx + bh * NQQ * 64;
        #pragma unroll
        for (int i = 0; i < 4; i++) {
            int qg = min(q0 + 4 * tq + i, NQQ - 1);
            float4 A = *(const float4*)&rxb[qg * 64 + 4 * tx];
            float4 B = *(const float4*)&rxb[qg * 64 + 32 + 4 * tx];
            rxr[i][0] = A.x; rxr[i][1] = A.y; rxr[i][2] = A.z; rxr[i][3] = A.w;
            rxr[i][4] = B.x; rxr[i][5] = B.y; rxr[i][6] = B.z; rxr[i][7] = B.w;
        }
    }

    int lk4 = (tid & 7) * 4;
    int lr16 = tid >> 3;          // 0..15
    const float* kb = g_kT + bh * 32 * HWK;
    const float* vbp = g_v + (long long)b * HWK * EE + h * HDIM;
    const float* ryp = g_ryT + bh * 64 * NQQ;
    int ryq = min(q0 + tid, NQQ - 1);

    int gp0 = sp * 16;

    // Prologue: pair gp0
    {
        int k0 = gp0 * 64;
        *(float4*)&Ks[lr16 * 32 + lk4]          = *(const float4*)&kb[lr16 * HWK + k0 + lk4];
        *(float4*)&Ks[(lr16 + 16) * 32 + lk4]   = *(const float4*)&kb[(lr16 + 16) * HWK + k0 + lk4];
        *(float4*)&Ks[1024 + lr16 * 32 + lk4]        = *(const float4*)&kb[lr16 * HWK + k0 + 32 + lk4];
        *(float4*)&Ks[1024 + (lr16 + 16) * 32 + lk4] = *(const float4*)&kb[(lr16 + 16) * HWK + k0 + 32 + lk4];
        *(float4*)&Vs[lr16 * 32 + lk4]        = *(const float4*)&vbp[(k0 + lr16) * EE + lk4];
        *(float4*)&Vs[(lr16 + 16) * 32 + lk4] = *(const float4*)&vbp[(k0 + lr16 + 16) * EE + lk4];
        *(float4*)&Vs[(lr16 + 32) * 32 + lk4] = *(const float4*)&vbp[(k0 + lr16 + 32) * EE + lk4];
        *(float4*)&Vs[(lr16 + 48) * 32 + lk4] = *(const float4*)&vbp[(k0 + lr16 + 48) * EE + lk4];
        if (tid < 64) ryc[tid] = ryp[gp0 * NQQ + ryq];
    }
    __syncthreads();

    u64 o2[4][2] = {};
    float l_acc[4] = {0.0f, 0.0f, 0.0f, 0.0f};

    for (int pr = 0; pr < 16; pr++) {
        int gp = gp0 + pr;

        // prefetch next K + ry into registers (live through GEMM1 only)
        float4 ka0, ka1, kc0, kc1; float ryr = 0.0f;
        if (pr < 15) {
            int k0n = (gp + 1) * 64;
            ka0 = *(const float4*)&kb[lr16 * HWK + k0n + lk4];
            ka1 = *(const float4*)&kb[(lr16 + 16) * HWK + k0n + lk4];
            kc0 = *(const float4*)&kb[lr16 * HWK + k0n + 32 + lk4];
            kc1 = *(const float4*)&kb[(lr16 + 16) * HWK + k0n + 32 + lk4];
            if (tid < 64) ryr = ryp[(gp + 1) * NQQ + ryq];
        }

        // ---- fused GEMM1 over both 32-key chunks ----
        u64 sA[4][2] = {}, sB[4][2] = {};
        #pragma unroll 8
        for (int kk = 0; kk < 32; kk++) {
            float4 qv = *(const float4*)&QsT[kk * 64 + 4 * tq];
            ulonglong2 kpa = *(const ulonglong2*)&Ks[kk * 32 + 4 * tx];
            ulonglong2 kpb = *(const ulonglong2*)&Ks[1024 + kk * 32 + 4 * tx];
            float qr[4] = {qv.x, qv.y, qv.z, qv.w};
            #pragma unroll
            for (int i = 0; i < 4; i++) {
                u64 qd = dup2(qr[i]);
                sA[i][0] = ffma2(qd, kpa.x, sA[i][0]);
                sA[i][1] = ffma2(qd, kpa.y, sA[i][1]);
                sB[i][0] = ffma2(qd, kpb.x, sB[i][0]);
                sB[i][1] = ffma2(qd, kpb.y, sB[i][1]);
            }
        }
        float s[4][8];
        #pragma unroll
        for (int i = 0; i < 4; i++) {
            float2 a0 = unpk2(sA[i][0]); float2 a1 = unpk2(sA[i][1]);
            float2 b0 = unpk2(sB[i][0]); float2 b1 = unpk2(sB[i][1]);
            s[i][0] = a0.x; s[i][1] = a0.y; s[i][2] = a1.x; s[i][3] = a1.y;
            s[i][4] = b0.x; s[i][5] = b0.y; s[i][6] = b1.x; s[i][7] = b1.y;
        }
        // bias (ry + rx regs) + direct exp2; local row sums
        float ry4[4];
        #pragma unroll
        for (int i = 0; i < 4; i++) ry4[i] = ryc[4 * tq + i];
        #pragma unroll
        for (int i = 0; i < 4; i++) {
            float sm_ = 0.0f;
            #pragma unroll
            for (int j = 0; j < 8; j++) {
                float p = fexp2(s[i][j] + ry4[i] + rxr[i][j]);
                s[i][j] = p;
                sm_ += p;
            }
            l_acc[i] += sm_;
        }

        // ---- P store: rows 0..31 at swz, rows 32..63 at swz^32 ----
        #pragma unroll
        for (int j = 0; j < 4; j++)
            *(float4*)&ST[(4 * tx + j) * 68 + swz] =
                make_float4(s[0][j], s[1][j], s[2][j], s[3][j]);
        #pragma unroll
        for (int j = 0; j < 4; j++)
            *(float4*)&ST[(32 + 4 * tx + j) * 68 + (swz ^ 32)] =
                make_float4(s[0][4 + j], s[1][4 + j], s[2][4 + j], s[3][4 + j]);
        __syncthreads();   // barrier 1: P visible; GEMM1 done -> K free

        // store prefetched K + ry
        if (pr < 15) {
            *(float4*)&Ks[lr16 * 32 + lk4]          = ka0;
            *(float4*)&Ks[(lr16 + 16) * 32 + lk4]   = ka1;
            *(float4*)&Ks[1024 + lr16 * 32 + lk4]        = kc0;
            *(float4*)&Ks[1024 + (lr16 + 16) * 32 + lk4] = kc1;
            if (tid < 64) ryc[tid] = ryr;
        }

        // prefetch next V (live through GEMM2 only; latency covered by GEMM2)
        float4 va0, va1, vc0, vc1;
        if (pr < 15) {
            int k0n = (gp + 1) * 64;
            va0 = *(const float4*)&vbp[(k0n + lr16) * EE + lk4];
            va1 = *(const float4*)&vbp[(k0n + lr16 + 16) * EE + lk4];
            vc0 = *(const float4*)&vbp[(k0n + lr16 + 32) * EE + lk4];
            vc1 = *(const float4*)&vbp[(k0n + lr16 + 48) * EE + lk4];
        }

        // ---- GEMM2 over 64 keys ----
        #pragma unroll 8
        for (int kk = 0; kk < 64; kk++) {
            float4 pv = *(const float4*)&ST[kk * 68 +
                            4 * ((tq ^ (kk >> 2)) & 15)];
            ulonglong2 vp = *(const ulonglong2*)&Vs[kk * 32 + 4 * tx];
            float pr4[4] = {pv.x, pv.y, pv.z, pv.w};
            #pragma unroll
            for (int i = 0; i < 4; i++) {
                u64 pd = dup2(pr4[i]);
                o2[i][0] = ffma2(pd, vp.x, o2[i][0]);
                o2[i][1] = ffma2(pd, vp.y, o2[i][1]);
            }
        }
        __syncthreads();   // barrier 2: GEMM2 done -> V/ST free

        // store prefetched V
        if (pr < 15) {
            *(float4*)&Vs[lr16 * 32 + lk4]        = va0;
            *(float4*)&Vs[(lr16 + 16) * 32 + lk4] = va1;
            *(float4*)&Vs[(lr16 + 32) * 32 + lk4] = vc0;
            *(float4*)&Vs[(lr16 + 48) * 32 + lk4] = vc1;
        }
    }

    // final l reduction across the 8 tx lanes
    #pragma unroll
    for (int d = 1; d < 8; d <<= 1)
        #pragma unroll
        for (int r = 0; r < 4; r++)
            l_acc[r] += __shfl_xor_sync(0xffffffffu, l_acc[r], d);

    // epilogue: unnormalized partials + l
    long long po_off = (((long long)sp * BB + b) * NH + h) * QPAD * HDIM;
    long long ml_off = (((long long)sp * BB + b) * NH + h) * QPAD;
    #pragma unroll
    for (int i = 0; i < 4; i++) {
        int q = q0 + 4 * tq + i;
        if (q < NQQ) {
            float2 lo = unpk2(o2[i][0]);
            float2 hi = unpk2(o2[i][1]);
            *(float4*)&g_po[po_off + (long long)q * HDIM + 4 * tx] =
                make_float4(lo.x, lo.y, hi.x, hi.y);
            if (tx == 0)
                g_pl[ml_off + q] = l_acc[i];
        }
    }
}

// ---------------------------------------------------------------------------
__global__ void combine_kernel(float* __restrict__ outp)
{
    const int PS = BB * NH * QPAD * HDIM;
    const int MS = BB * NH * QPAD;
    int t = blockIdx.x * 256 + threadIdx.x;
    int flat = t * 8;
    int b = flat / (NQQ * EE);
    int rem = flat - b * (NQQ * EE);
    int q = rem >> 8;
    int e = rem & 255;
    int h = e >> 5, d = e & 31;
    int po0 = ((b * NH + h) * QPAD + q) * HDIM + d;
    int ml0 = (b * NH + h) * QPAD + q;

    float den = 0.0f;
    #pragma unroll
    for (int sct = 0; sct < NSPLIT; sct++)
        den += g_pl[ml0 + sct * MS];
    float inv = 1.0f / den;

    float acc[8] = {};
    #pragma unroll
    for (int sct = 0; sct < NSPLIT; sct++) {
        float4 a0 = *(const float4*)&g_po[po0 + sct * PS];
        float4 a1 = *(const float4*)&g_po[po0 + sct * PS + 4];
        acc[0] += a0.x;  acc[1] += a0.y;
        acc[2] += a0.z;  acc[3] += a0.w;
        acc[4] += a1.x;  acc[5] += a1.y;
        acc[6] += a1.z;  acc[7] += a1.w;
    }
    *(float4*)&outp[flat] =
        make_float4(acc[0] * inv, acc[1] * inv, acc[2] * inv, acc[3] * inv);
    *(float4*)&outp[flat + 4] =
        make_float4(acc[4] * inv, acc[5] * inv, acc[6] * inv, acc[7] * inv);
}

// ---------------------------------------------------------------------------
extern "C" void kernel_launch(void* const* d_in, const int* in_sizes, int n_in,
                              void* d_out, int out_size)
{
    const float* query = (const float*)d_in[0];
    const float* key   = (const float*)d_in[1];
    const float* value = (const float*)d_in[2];
    const float* refp  = (const float*)d_in[3];
    const float* Wq = (const float*)d_in[4];  const float* bq = (const float*)d_in[5];
    const float* Wk = (const float*)d_in[6];  const float* bk = (const float*)d_in[7];
    const float* Wv = (const float*)d_in[8];  const float* bv = (const float*)d_in[9];
    const float* Wo = (const float*)d_in[10]; const float* bo = (const float*)d_in[11];
    const float* W1x = (const float*)d_in[12]; const float* b1x = (const float*)d_in[13];
    const float* W2x = (const float*)d_in[14];
    const float* W1y = (const float*)d_in[15]; const float* b1y = (const float*)d_in[16];
    const float* W2y = (const float*)d_in[17];
    float* out = (float*)d_out;

    float *pqT, *pkT, *pv, *patt;
    cudaGetSymbolAddress((void**)&pqT, g_qT);
    cudaGetSymbolAddress((void**)&pkT, g_kT);
    cudaGetSymbolAddress((void**)&pv, g_v);
    cudaGetSymbolAddress((void**)&patt, g_att);

    static int attr_done = 0;
    if (!attr_done) {
        cudaFuncSetAttribute(attn_kernel,
                             cudaFuncAttributeMaxDynamicSharedMemorySize,
                             ATTN_SMEM_FLOATS * 4);
        attr_done = 1;
    }

    gemm_bias_kernel<1><<<dim3(29, 4), 256>>>(query, Wq, bq, pqT, BB * NQQ,
                                              NQQ, QSCALE_F * LOG2E_F);
    gemm_bias_kernel<1><<<dim3(128, 4), 256>>>(key, Wk, bk, pkT, BB * HWK,
                                               HWK, 1.0f);
    gemm_bias_kernel<0><<<dim3(128, 4), 256>>>(value, Wv, bv, pv, BB * HWK,
                                               HWK, 1.0f);

    rpe_kernel<<<dim3(450, 2), 128>>>(refp, W1x, b1x, W2x, W1y, b1y, W2y);

    attn_kernel<<<dim3(15, NH, BB * NSPLIT), 128, ATTN_SMEM_FLOATS * 4>>>();

    combine_kernel<<<225, 256>>>(patt);

    gemm_bias_kernel<0><<<dim3(29, 4), 256>>>(patt, Wo, bo, out, BB * NQQ,
                                              NQQ, 1.0f);
}

// round 17
// speedup vs baseline: 1.0009x; 1.0009x over previous
#include <cuda_runtime.h>
#include <math.h>

#define BB    2
#define NQQ   900
#define EE    256
#define NH    8
#define HDIM  32
#define HWK   4096
#define RPEH  512
#define RPEH2 256
#define LOG2E_F 1.4426950408889634f
#define QSCALE_F 0.17677669529663687f
#define NSPLIT 4
#define QPAD   960
#define RXN   (BB * NH * NQQ * 64)

__device__ float g_qT[BB * NH * HDIM * NQQ + 1024];
__device__ float g_kT[BB * NH * HDIM * HWK];
__device__ float g_v [BB * HWK * EE];
__device__ float g_rx[RXN];
__device__ float g_rx2[RXN];
__device__ float g_ryT[RXN];
__device__ float g_ryT2[RXN];
__device__ float g_att[BB * NQQ * EE];
__device__ float g_po[NSPLIT * BB * NH * QPAD * HDIM];
__device__ float g_pl[NSPLIT * BB * NH * QPAD];

typedef unsigned long long u64;

__device__ __forceinline__ float fexp2(float x) {
    float y; asm("ex2.approx.ftz.f32 %0, %1;" : "=f"(y) : "f"(x)); return y;
}
__device__ __forceinline__ u64 ffma2(u64 a, u64 b, u64 c) {
    u64 d; asm("fma.rn.f32x2 %0, %1, %2, %3;" : "=l"(d) : "l"(a), "l"(b), "l"(c)); return d;
}
__device__ __forceinline__ u64 fmul2(u64 a, u64 b) {
    u64 d; asm("mul.rn.f32x2 %0, %1, %2;" : "=l"(d) : "l"(a), "l"(b)); return d;
}
__device__ __forceinline__ u64 dup2(float x) {
    u64 r; asm("mov.b64 %0, {%1, %1};" : "=l"(r) : "f"(x)); return r;
}
__device__ __forceinline__ float2 unpk2(u64 v) {
    float2 r; asm("mov.b64 {%0, %1}, %2;" : "=f"(r.x), "=f"(r.y) : "l"(v)); return r;
}
__device__ __forceinline__ float logdelta(float d) {
    float l = log2f(fabsf(d) + 1.0f) * (1.0f / 3.0f);
    return copysignf(l, d);
}

// ---------------------------------------------------------------------------
template<int TMODE>
__global__ void gemm_bias_kernel(const float* __restrict__ A,
                                 const float* __restrict__ Wm,
                                 const float* __restrict__ bias,
                                 float* __restrict__ C,
                                 int M, int plane, float alpha)
{
    __shared__ __align__(16) float As[16][64];
    __shared__ __align__(16) float Ws[16][64];

    int tid = threadIdx.x;
    int m0 = blockIdx.x * 64;
    int n0 = blockIdx.y * 64;
    int tm = tid >> 4, tn = tid & 15;
    int lrow = tid >> 2, lkq = tid & 3;
    int wkk = tid >> 4, wnq = tid & 15;

    u64 acc2[4][2] = {};

    for (int k0 = 0; k0 < 256; k0 += 16) {
        float4 av = make_float4(0.f, 0.f, 0.f, 0.f);
        int m = m0 + lrow;
        if (m < M) av = *(const float4*)&A[m * 256 + k0 + 4 * lkq];
        As[4 * lkq + 0][lrow] = av.x;
        As[4 * lkq + 1][lrow] = av.y;
        As[4 * lkq + 2][lrow] = av.z;
        As[4 * lkq + 3][lrow] = av.w;
        *(float4*)&Ws[wkk][4 * wnq] =
            *(const float4*)&Wm[(k0 + wkk) * 256 + n0 + 4 * wnq];
        __syncthreads();

        #pragma unroll
        for (int kk = 0; kk < 16; kk++) {
            float4 a = *(const float4*)&As[kk][4 * tm];
            ulonglong2 w = *(const ulonglong2*)&Ws[kk][4 * tn];
            float ar[4] = {a.x, a.y, a.z, a.w};
            #pragma unroll
            for (int i = 0; i < 4; i++) {
                u64 ad = dup2(ar[i]);
                acc2[i][0] = ffma2(ad, w.x, acc2[i][0]);
                acc2[i][1] = ffma2(ad, w.y, acc2[i][1]);
            }
        }
        __syncthreads();
    }

    float4 bv = *(const float4*)&bias[n0 + 4 * tn];
    float o[4][4];
    #pragma unroll
    for (int i = 0; i < 4; i++) {
        float2 lo = unpk2(acc2[i][0]);
        float2 hi = unpk2(acc2[i][1]);
        o[i][0] = alpha * (lo.x + bv.x);
        o[i][1] = alpha * (lo.y + bv.y);
        o[i][2] = alpha * (hi.x + bv.z);
        o[i][3] = alpha * (hi.y + bv.w);
    }

    if (TMODE == 0) {
        #pragma unroll
        for (int i = 0; i < 4; i++) {
            int m = m0 + 4 * tm + i;
            if (m < M)
                *(float4*)&C[m * 256 + n0 + 4 * tn] =
                    make_float4(o[i][0], o[i][1], o[i][2], o[i][3]);
        }
    } else {
        __shared__ float Ts[64][65];
        #pragma unroll
        for (int i = 0; i < 4; i++)
            #pragma unroll
            for (int j = 0; j < 4; j++)
                Ts[4 * tn + j][4 * tm + i] = o[i][j];
        __syncthreads();
        for (int idx = tid; idx < 4096; idx += 256) {
            int ml = idx & 63, nl = idx >> 6;
            int m = m0 + ml;
            if (m < M) {
                int bq = m / plane;
                int mm = m - bq * plane;
                int n = n0 + nl;
                int row = (bq * NH + (n >> 5)) * 32 + (n & 31);
                C[(long long)row * plane + mm] = Ts[nl][ml];
            }
        }
    }
}

// ---------------------------------------------------------------------------
// RPE MLP, hidden-split: grid (450, 2 axes, 2 halves), 128 threads.
// Each block handles 256 of the 512 hidden units (second layer is linear in
// the hidden sum, relu is per-unit => exact split). Half 1 writes partial
// arrays; rpe_merge sums them.
// ---------------------------------------------------------------------------
__global__ void rpe_kernel(const float* __restrict__ refp,
                           const float* __restrict__ W1x, const float* __restrict__ b1x,
                           const float* __restrict__ W2x,
                           const float* __restrict__ W1y, const float* __restrict__ b1y,
                           const float* __restrict__ W2y)
{
    __shared__ __align__(16) float4 sW1p[RPEH2];
    __shared__ __align__(16) float sW2[RPEH2 * 8];

    int tid = threadIdx.x;
    int axis = blockIdx.y;
    int half = blockIdx.z;
    int h0 = half * RPEH2;
    const float* W1 = axis ? W1y : W1x;
    const float* b1 = axis ? b1y : b1x;
    const float* W2 = axis ? W2y : W2x;

    for (int i = tid; i < RPEH2; i += 128)
        sW1p[i] = make_float4(W1[h0 + i], W1[RPEH + h0 + i], b1[h0 + i], 0.0f);
    for (int i = tid; i < RPEH2 * 8; i += 128)
        sW2[i] = W2[h0 * 8 + i];
    __syncthreads();

    int bq = blockIdx.x * 4 + (tid >> 5);
    int b = bq / NQQ, q = bq - b * NQQ;
    float4 r = *(const float4*)&refp[bq * 4];
    int lane = tid & 31;

    float ctr = axis ? r.y : r.x;
    float sz  = axis ? r.w : r.z;
    float lo = (ctr - 0.5f * sz) * 1024.0f;
    float hi = (ctr + 0.5f * sz) * 1024.0f;
    float posA = (lane + 0.5f) * 16.0f;
    float posB = (lane + 32.5f) * 16.0f;
    float d1a = logdelta(lo - posA), d2a = logdelta(hi - posA);
    float d1b = logdelta(lo - posB), d2b = logdelta(hi - posB);

    u64 a0[4] = {}, a1[4] = {};
    #pragma unroll 4
    for (int hh = 0; hh < RPEH2; hh++) {
        float4 w = sW1p[hh];
        float v0 = fmaxf(fmaf(d1a, w.x, fmaf(d2a, w.y, w.z)), 0.0f);
        float v1 = fmaxf(fmaf(d1b, w.x, fmaf(d2b, w.y, w.z)), 0.0f);
        u64 v0d = dup2(v0), v1d = dup2(v1);
        ulonglong2 wlo = *(const ulonglong2*)&sW2[hh * 8];
        ulonglong2 whi = *(const ulonglong2*)&sW2[hh * 8 + 4];
        a0[0] = ffma2(v0d, wlo.x, a0[0]);  a0[1] = ffma2(v0d, wlo.y, a0[1]);
        a0[2] = ffma2(v0d, whi.x, a0[2]);  a0[3] = ffma2(v0d, whi.y, a0[3]);
        a1[0] = ffma2(v1d, wlo.x, a1[0]);  a1[1] = ffma2(v1d, wlo.y, a1[1]);
        a1[2] = ffma2(v1d, whi.x, a1[2]);  a1[3] = ffma2(v1d, whi.y, a1[3]);
    }

    float o0[8], o1[8];
    #pragma unroll
    for (int c = 0; c < 4; c++) {
        float2 x0 = unpk2(a0[c]); float2 x1 = unpk2(a1[c]);
        o0[2*c] = x0.x * LOG2E_F;  o0[2*c+1] = x0.y * LOG2E_F;
        o1[2*c] = x1.x * LOG2E_F;  o1[2*c+1] = x1.y * LOG2E_F;
    }
    float* rxout = half ? g_rx2 : g_rx;
    float* ryout = half ? g_ryT2 : g_ryT;
    long long bh = (long long)b * NH;
    #pragma unroll
    for (int hd = 0; hd < 8; hd++) {
        if (axis == 0) {
            rxout[((bh + hd) * NQQ + q) * 64 + lane]      = o0[hd];
            rxout[((bh + hd) * NQQ + q) * 64 + lane + 32] = o1[hd];
        } else {
            ryout[((bh + hd) * 64 + lane)      * NQQ + q] = o0[hd];
            ryout[((bh + hd) * 64 + lane + 32) * NQQ + q] = o1[hd];
        }
    }
}

// Merge the two hidden-half partials (rx and ryT). RXN = 921600 floats each.
__global__ void rpe_merge()
{
    int i = (blockIdx.x * 256 + threadIdx.x) * 4;
    if (i < RXN) {
        float4 a = *(const float4*)&g_rx[i];
        float4 b = *(const float4*)&g_rx2[i];
        *(float4*)&g_rx[i] = make_float4(a.x + b.x, a.y + b.y, a.z + b.z, a.w + b.w);
        float4 c = *(const float4*)&g_ryT[i];
        float4 d = *(const float4*)&g_ryT2[i];
        *(float4*)&g_ryT[i] = make_float4(c.x + d.x, c.y + d.y, c.z + d.z, c.w + d.w);
    }
}

// ---------------------------------------------------------------------------
// Fused attention (R14 402us version, byte-identical): pair-fused loop,
// no online softmax, rxsT in smem, 3 blocks/SM.
// ---------------------------------------------------------------------------
#define OFF_K    2048
#define OFF_V    4096
#define OFF_ST   6144
#define OFF_RX   10496
#define OFF_RY   14848
#define ATTN_SMEM_FLOATS 14912

__global__ void __launch_bounds__(128, 3) attn_kernel()
{
    extern __shared__ __align__(16) float sm[];
    float* QsT  = sm;
    float* Ks   = sm + OFF_K;
    float* Vs   = sm + OFF_V;
    float* ST   = sm + OFF_ST;
    float* rxsT = sm + OFF_RX;
    float* ryc  = sm + OFF_RY;

    int tid = threadIdx.x;
    int qt = blockIdx.x, h = blockIdx.y;
    int b = blockIdx.z >> 2, sp = blockIdx.z & 3;
    int q0 = qt * 64;
    int tq = tid >> 3, tx = tid & 7;
    int swz = 4 * ((tq ^ tx) & 15);
    long long bh = (long long)b * NH + h;

    // Q tile
    {
        int q4 = (tid & 15) * 4;
        int dr = tid >> 4;
        const float* qb = g_qT + bh * 32 * NQQ;
        #pragma unroll
        for (int r2 = 0; r2 < 4; r2++) {
            int d = dr + 8 * r2;
            float4 val = make_float4(0.f, 0.f, 0.f, 0.f);
            if (q0 + q4 < NQQ) val = *(const float4*)&qb[d * NQQ + q0 + q4];
            *(float4*)&QsT[d * 64 + q4] = val;
        }
    }
    // rx tile, transposed [w][q] with XOR swizzle on q-quad
    {
        const float* rxb = g_rx + bh * NQQ * 64;
        for (int idx = tid; idx < 64 * 16; idx += 128) {
            int q = idx >> 4, w4 = (idx & 15) * 4;
            int qg = min(q0 + q, NQQ - 1);
            float4 v = *(const float4*)&rxb[qg * 64 + w4];
            int col = (q & 3) + 4 * (((q >> 2) ^ (idx & 7)) & 15);
            rxsT[(w4 + 0) * 68 + col] = v.x;
            rxsT[(w4 + 1) * 68 + col] = v.y;
            rxsT[(w4 + 2) * 68 + col] = v.z;
            rxsT[(w4 + 3) * 68 + col] = v.w;
        }
    }

    int lk4 = (tid & 7) * 4;
    int lr16 = tid >> 3;
    const float* kb = g_kT + bh * 32 * HWK;
    const float* vbp = g_v + (long long)b * HWK * EE + h * HDIM;
    const float* ryp = g_ryT + bh * 64 * NQQ;
    int ryq = min(q0 + tid, NQQ - 1);

    int gp0 = sp * 16;

    // Prologue: pair gp0
    {
        int k0 = gp0 * 64;
        *(float4*)&Ks[lr16 * 32 + lk4]          = *(const float4*)&kb[lr16 * HWK + k0 + lk4];
        *(float4*)&Ks[(lr16 + 16) * 32 + lk4]   = *(const float4*)&kb[(lr16 + 16) * HWK + k0 + lk4];
        *(float4*)&Ks[1024 + lr16 * 32 + lk4]        = *(const float4*)&kb[lr16 * HWK + k0 + 32 + lk4];
        *(float4*)&Ks[1024 + (lr16 + 16) * 32 + lk4] = *(const float4*)&kb[(lr16 + 16) * HWK + k0 + 32 + lk4];
        *(float4*)&Vs[lr16 * 32 + lk4]        = *(const float4*)&vbp[(k0 + lr16) * EE + lk4];
        *(float4*)&Vs[(lr16 + 16) * 32 + lk4] = *(const float4*)&vbp[(k0 + lr16 + 16) * EE + lk4];
        *(float4*)&Vs[(lr16 + 32) * 32 + lk4] = *(const float4*)&vbp[(k0 + lr16 + 32) * EE + lk4];
        *(float4*)&Vs[(lr16 + 48) * 32 + lk4] = *(const float4*)&vbp[(k0 + lr16 + 48) * EE + lk4];
        if (tid < 64) ryc[tid] = ryp[gp0 * NQQ + ryq];
    }
    __syncthreads();

    u64 o2[4][2] = {};
    float l_acc[4] = {0.0f, 0.0f, 0.0f, 0.0f};

    for (int pr = 0; pr < 16; pr++) {
        int gp = gp0 + pr;

        float4 ka0, ka1, kc0, kc1, va0, va1, vc0, vc1; float ryr = 0.0f;
        if (pr < 15) {
            int k0n = (gp + 1) * 64;
            ka0 = *(const float4*)&kb[lr16 * HWK + k0n + lk4];
            ka1 = *(const float4*)&kb[(lr16 + 16) * HWK + k0n + lk4];
            kc0 = *(const float4*)&kb[lr16 * HWK + k0n + 32 + lk4];
            kc1 = *(const float4*)&kb[(lr16 + 16) * HWK + k0n + 32 + lk4];
            va0 = *(const float4*)&vbp[(k0n + lr16) * EE + lk4];
            va1 = *(const float4*)&vbp[(k0n + lr16 + 16) * EE + lk4];
            vc0 = *(const float4*)&vbp[(k0n + lr16 + 32) * EE + lk4];
            vc1 = *(const float4*)&vbp[(k0n + lr16 + 48) * EE + lk4];
            if (tid < 64) ryr = ryp[(gp + 1) * NQQ + ryq];
        }

        // ---- fused GEMM1 over both 32-key chunks ----
        u64 sA[4][2] = {}, sB[4][2] = {};
        #pragma unroll 8
        for (int kk = 0; kk < 32; kk++) {
            float4 qv = *(const float4*)&QsT[kk * 64 + 4 * tq];
            ulonglong2 kpa = *(const ulonglong2*)&Ks[kk * 32 + 4 * tx];
            ulonglong2 kpb = *(const ulonglong2*)&Ks[1024 + kk * 32 + 4 * tx];
            float qr[4] = {qv.x, qv.y, qv.z, qv.w};
            #pragma unroll
            for (int i = 0; i < 4; i++) {
                u64 qd = dup2(qr[i]);
                sA[i][0] = ffma2(qd, kpa.x, sA[i][0]);
                sA[i][1] = ffma2(qd, kpa.y, sA[i][1]);
                sB[i][0] = ffma2(qd, kpb.x, sB[i][0]);
                sB[i][1] = ffma2(qd, kpb.y, sB[i][1]);
            }
        }
        float s[4][8];
        #pragma unroll
        for (int i = 0; i < 4; i++) {
            float2 a0 = unpk2(sA[i][0]); float2 a1 = unpk2(sA[i][1]);
            float2 b0 = unpk2(sB[i][0]); float2 b1 = unpk2(sB[i][1]);
            s[i][0] = a0.x; s[i][1] = a0.y; s[i][2] = a1.x; s[i][3] = a1.y;
            s[i][4] = b0.x; s[i][5] = b0.y; s[i][6] = b1.x; s[i][7] = b1.y;
        }
        // bias + direct exp2 (no max subtraction; scores provably tiny)
        float ry4[4];
        #pragma unroll
        for (int i = 0; i < 4; i++) ry4[i] = ryc[4 * tq + i];
        #pragma unroll
        for (int j = 0; j < 4; j++) {
            float4 rvA = *(const float4*)&rxsT[(4 * tx + j) * 68 + swz];
            float4 rvB = *(const float4*)&rxsT[(32 + 4 * tx + j) * 68 + swz];
            s[0][j] = fexp2(s[0][j] + ry4[0] + rvA.x);
            s[0][4 + j] = fexp2(s[0][4 + j] + ry4[0] + rvB.x);
            s[1][j] = fexp2(s[1][j] + ry4[1] + rvA.y);
            s[1][4 + j] = fexp2(s[1][4 + j] + ry4[1] + rvB.y);
            s[2][j] = fexp2(s[2][j] + ry4[2] + rvA.z);
            s[2][4 + j] = fexp2(s[2][4 + j] + ry4[2] + rvB.z);
            s[3][j] = fexp2(s[3][j] + ry4[3] + rvA.w);
            s[3][4 + j] = fexp2(s[3][4 + j] + ry4[3] + rvB.w);
        }
        #pragma unroll
        for (int r = 0; r < 4; r++) {
            float sm_ = ((s[r][0] + s[r][1]) + (s[r][2] + s[r][3]))
                      + ((s[r][4] + s[r][5]) + (s[r][6] + s[r][7]));
            l_acc[r] += sm_;
        }

        // ---- P store ----
        #pragma unroll
        for (int j = 0; j < 4; j++)
            *(float4*)&ST[(4 * tx + j) * 68 + swz] =
                make_float4(s[0][j], s[1][j], s[2][j], s[3][j]);
        #pragma unroll
        for (int j = 0; j < 4; j++)
            *(float4*)&ST[(32 + 4 * tx + j) * 68 + (swz ^ 32)] =
                make_float4(s[0][4 + j], s[1][4 + j], s[2][4 + j], s[3][4 + j]);
        __syncthreads();

        if (pr < 15) {
            *(float4*)&Ks[lr16 * 32 + lk4]          = ka0;
            *(float4*)&Ks[(lr16 + 16) * 32 + lk4]   = ka1;
            *(float4*)&Ks[1024 + lr16 * 32 + lk4]        = kc0;
            *(float4*)&Ks[1024 + (lr16 + 16) * 32 + lk4] = kc1;
            if (tid < 64) ryc[tid] = ryr;
        }

        // ---- GEMM2 over 64 keys ----
        #pragma unroll 8
        for (int kk = 0; kk < 64; kk++) {
            float4 pv = *(const float4*)&ST[kk * 68 +
                            4 * ((tq ^ (kk >> 2)) & 15)];
            ulonglong2 vp = *(const ulonglong2*)&Vs[kk * 32 + 4 * tx];
            float pr4[4] = {pv.x, pv.y, pv.z, pv.w};
            #pragma unroll
            for (int i = 0; i < 4; i++) {
                u64 pd = dup2(pr4[i]);
                o2[i][0] = ffma2(pd, vp.x, o2[i][0]);
                o2[i][1] = ffma2(pd, vp.y, o2[i][1]);
            }
        }
        __syncthreads();

        if (pr < 15) {
            *(float4*)&Vs[lr16 * 32 + lk4]        = va0;
            *(float4*)&Vs[(lr16 + 16) * 32 + lk4] = va1;
            *(float4*)&Vs[(lr16 + 32) * 32 + lk4] = vc0;
            *(float4*)&Vs[(lr16 + 48) * 32 + lk4] = vc1;
        }
    }

    #pragma unroll
    for (int d = 1; d < 8; d <<= 1)
        #pragma unroll
        for (int r = 0; r < 4; r++)
            l_acc[r] += __shfl_xor_sync(0xffffffffu, l_acc[r], d);

    long long po_off = (((long long)sp * BB + b) * NH + h) * QPAD * HDIM;
    long long ml_off = (((long long)sp * BB + b) * NH + h) * QPAD;
    #pragma unroll
    for (int i = 0; i < 4; i++) {
        int q = q0 + 4 * tq + i;
        if (q < NQQ) {
            float2 lo = unpk2(o2[i][0]);
            float2 hi = unpk2(o2[i][1]);
            *(float4*)&g_po[po_off + (long long)q * HDIM + 4 * tx] =
                make_float4(lo.x, lo.y, hi.x, hi.y);
            if (tx == 0)
                g_pl[ml_off + q] = l_acc[i];
        }
    }
}

// ---------------------------------------------------------------------------
__global__ void combine_kernel(float* __restrict__ outp)
{
    const int PS = BB * NH * QPAD * HDIM;
    const int MS = BB * NH * QPAD;
    int t = blockIdx.x * 256 + threadIdx.x;
    int flat = t * 8;
    int b = flat / (NQQ * EE);
    int rem = flat - b * (NQQ * EE);
    int q = rem >> 8;
    int e = rem & 255;
    int h = e >> 5, d = e & 31;
    int po0 = ((b * NH + h) * QPAD + q) * HDIM + d;
    int ml0 = (b * NH + h) * QPAD + q;

    float den = 0.0f;
    #pragma unroll
    for (int sct = 0; sct < NSPLIT; sct++)
        den += g_pl[ml0 + sct * MS];
    float inv = 1.0f / den;

    float acc[8] = {};
    #pragma unroll
    for (int sct = 0; sct < NSPLIT; sct++) {
        float4 a0 = *(const float4*)&g_po[po0 + sct * PS];
        float4 a1 = *(const float4*)&g_po[po0 + sct * PS + 4];
        acc[0] += a0.x;  acc[1] += a0.y;
        acc[2] += a0.z;  acc[3] += a0.w;
        acc[4] += a1.x;  acc[5] += a1.y;
        acc[6] += a1.z;  acc[7] += a1.w;
    }
    *(float4*)&outp[flat] =
        make_float4(acc[0] * inv, acc[1] * inv, acc[2] * inv, acc[3] * inv);
    *(float4*)&outp[flat + 4] =
        make_float4(acc[4] * inv, acc[5] * inv, acc[6] * inv, acc[7] * inv);
}

// ---------------------------------------------------------------------------
extern "C" void kernel_launch(void* const* d_in, const int* in_sizes, int n_in,
                              void* d_out, int out_size)
{
    const float* query = (const float*)d_in[0];
    const float* key   = (const float*)d_in[1];
    const float* value = (const float*)d_in[2];
    const float* refp  = (const float*)d_in[3];
    const float* Wq = (const float*)d_in[4];  const float* bq = (const float*)d_in[5];
    const float* Wk = (const float*)d_in[6];  const float* bk = (const float*)d_in[7];
    const float* Wv = (const float*)d_in[8];  const float* bv = (const float*)d_in[9];
    const float* Wo = (const float*)d_in[10]; const float* bo = (const float*)d_in[11];
    const float* W1x = (const float*)d_in[12]; const float* b1x = (const float*)d_in[13];
    const float* W2x = (const float*)d_in[14];
    const float* W1y = (const float*)d_in[15]; const float* b1y = (const float*)d_in[16];
    const float* W2y = (const float*)d_in[17];
    float* out = (float*)d_out;

    float *pqT, *pkT, *pv, *patt;
    cudaGetSymbolAddress((void**)&pqT, g_qT);
    cudaGetSymbolAddress((void**)&pkT, g_kT);
    cudaGetSymbolAddress((void**)&pv, g_v);
    cudaGetSymbolAddress((void**)&patt, g_att);

    static int attr_done = 0;
    if (!attr_done) {
        cudaFuncSetAttribute(attn_kernel,
                             cudaFuncAttributeMaxDynamicSharedMemorySize,
                             ATTN_SMEM_FLOATS * 4);
        attr_done = 1;
    }

    gemm_bias_kernel<1><<<dim3(29, 4), 256>>>(query, Wq, bq, pqT, BB * NQQ,
                                              NQQ, QSCALE_F * LOG2E_F);
    gemm_bias_kernel<1><<<dim3(128, 4), 256>>>(key, Wk, bk, pkT, BB * HWK,
                                               HWK, 1.0f);
    gemm_bias_kernel<0><<<dim3(128, 4), 256>>>(value, Wv, bv, pv, BB * HWK,
                                               HWK, 1.0f);

    rpe_kernel<<<dim3(450, 2, 2), 128>>>(refp, W1x, b1x, W2x, W1y, b1y, W2y);
    rpe_merge<<<900, 256>>>();

    attn_kernel<<<dim3(15, NH, BB * NSPLIT), 128, ATTN_SMEM_FLOATS * 4>>>();

    combine_kernel<<<225, 256>>>(patt);

    gemm_bias_kernel<0><<<dim3(29, 4), 256>>>(patt, Wo, bo, out, BB * NQQ,
                                              NQQ, 1.0f);
}